// round 13
// baseline (speedup 1.0000x reference)
#include <cuda_runtime.h>

// FWHT, 4096 rows x 16384 fp32. Persistent CTAs (grid=148, 1/SM), 1024 thr.
// R6 dataflow (best measured) + DISTRIBUTED register prefetch: the next row's
// four LDG.128 are spread across the barrier sections (one per phase) so the
// L1tex/DRAM request stream is smooth instead of a top-of-loop burst.
// Barriers pin the placement in SASS.
// Per-row dataflow:
//   P1: regs H16 over bits {13,12,1,0}  (float4 LDG; vector lanes = bits 1,0)
//   X1 -> P2: regs H16 over bits {11..8}  (same-address writeback)
//   X2 -> P3: regs H16 over bits {7..4}
//   shfl stages over bits {3,2}; scale 2^-7; coalesced STG.
// Swizzle phys(i) = i + 16*(i>>8): injective, 16B-aligned, conflict-free for
// all four smem patterns (verified R5-R9).

#define N_ELEM 16384
#define THREADS 1024
#define SMEM_FLOATS 17408  // max phys index 16383 + 16*63 = 17391
#define GRID 148

__device__ __forceinline__ int physz(int i) { return i + ((i >> 8) << 4); }

template <int N>
__device__ __forceinline__ void hadN(float* v) {
#pragma unroll
    for (int s = 1; s < N; s <<= 1) {
#pragma unroll
        for (int i = 0; i < N; i++) {
            if ((i & s) == 0) {
                float a = v[i];
                float b = v[i | s];
                v[i]     = a + b;
                v[i | s] = a - b;
            }
        }
    }
}

__global__ __launch_bounds__(THREADS, 1)
void fwht_kernel(const float* __restrict__ in, float* __restrict__ out,
                 int nrows) {
    extern __shared__ float sh[];
    const int t = threadIdx.x;
    const int l = t & 31;

    // Immediate-foldable bases:
    // P1: phys(j<<12 | t<<2)                = pa  + j*4352
    // P2: phys((t>>8)<<12 | r<<8 | (t&255)) = pb1 + r*272
    // P3: phys((t>>4)<<8  | r<<4 | (t&15))  = pb2 + r*16
    const int pa  = (t << 2) + ((t >> 6) << 4);
    const int pb1 = physz(((t >> 8) << 12) | (t & 255));
    const int b2  = ((t >> 4) << 8) | (t & 15);
    const int pb2 = physz(b2);

    const float s3 = (l & 8) ? -1.0f : 1.0f;
    const float s2 = (l & 4) ? -1.0f : 1.0f;

    float v[16];

    int row = blockIdx.x;
    {
        const float4* __restrict__ p4 =
            reinterpret_cast<const float4*>(in + (size_t)row * N_ELEM + (t << 2));
#pragma unroll
        for (int j = 0; j < 4; j++) {
            float4 f = p4[(size_t)j << 10];
            v[4 * j + 0] = f.x; v[4 * j + 1] = f.y;
            v[4 * j + 2] = f.z; v[4 * j + 3] = f.w;
        }
    }

    while (row < nrows) {
        const int nextrow = row + GRID;
        const bool pre = (nextrow < nrows);
        const float4* __restrict__ pn4 =
            reinterpret_cast<const float4*>(in + (size_t)nextrow * N_ELEM + (t << 2));

        float4 f0, f1, f2, f3;

        // ---- prefetch piece 0 (used next iteration; covered by P1+B1)
        if (pre) f0 = pn4[0];

        // ---- P1: butterflies bits {13,12,1,0}; STS.128
        hadN<16>(v);
#pragma unroll
        for (int j = 0; j < 4; j++) {
            *reinterpret_cast<float4*>(&sh[pa + j * 4352]) =
                make_float4(v[4 * j + 0], v[4 * j + 1], v[4 * j + 2], v[4 * j + 3]);
        }
        __syncthreads();  // B1

        // ---- prefetch piece 1 (covered by P2+B2)
        if (pre) f1 = pn4[(size_t)1 << 10];

        // ---- P2: bits {11..8}; in-place (same-address) writeback
#pragma unroll
        for (int r = 0; r < 16; r++) v[r] = sh[pb1 + r * 272];
        hadN<16>(v);
#pragma unroll
        for (int r = 0; r < 16; r++) sh[pb1 + r * 272] = v[r];
        __syncthreads();  // B2

        // ---- prefetch piece 2 (covered by P3+shfl+stores)
        if (pre) f2 = pn4[(size_t)2 << 10];

        // ---- P3: bits {7..4}
#pragma unroll
        for (int r = 0; r < 16; r++) v[r] = sh[pb2 + r * 16];
        __syncthreads();  // B3: smem free for next iteration's P1 writes

        // ---- prefetch piece 3 (covered by hadN+shfl+stores)
        if (pre) f3 = pn4[(size_t)3 << 10];

        hadN<16>(v);

        // ---- bits {3,2} on lane bits 3,2 via shfl-xor sign trick
#pragma unroll
        for (int r = 0; r < 16; r++) {
            float q = __shfl_xor_sync(0xffffffffu, v[r], 8);
            v[r] = fmaf(s3, v[r], q);
        }
#pragma unroll
        for (int r = 0; r < 16; r++) {
            float q = __shfl_xor_sync(0xffffffffu, v[r], 4);
            v[r] = fmaf(s2, v[r], q);
        }

        // ---- scale 2^-7, coalesced store (full 64B sectors)
        float* __restrict__ pout = out + (size_t)row * N_ELEM;
#pragma unroll
        for (int r = 0; r < 16; r++)
            pout[b2 + (r << 4)] = v[r] * 0.0078125f;

        // ---- rotate pipeline into v
        if (pre) {
            v[0]  = f0.x; v[1]  = f0.y; v[2]  = f0.z; v[3]  = f0.w;
            v[4]  = f1.x; v[5]  = f1.y; v[6]  = f1.z; v[7]  = f1.w;
            v[8]  = f2.x; v[9]  = f2.y; v[10] = f2.z; v[11] = f2.w;
            v[12] = f3.x; v[13] = f3.y; v[14] = f3.z; v[15] = f3.w;
        }
        row = nextrow;
    }
}

extern "C" void kernel_launch(void* const* d_in, const int* in_sizes, int n_in,
                              void* d_out, int out_size) {
    const float* phi = (const float*)d_in[0];
    float* out = (float*)d_out;

    const size_t smem = SMEM_FLOATS * sizeof(float);  // 69632 B
    cudaFuncSetAttribute(fwht_kernel,
                         cudaFuncAttributeMaxDynamicSharedMemorySize,
                         (int)smem);

    const int nrows = in_sizes[0] / N_ELEM;  // 4096
    const int grid = nrows < GRID ? nrows : GRID;
    fwht_kernel<<<grid, THREADS, smem>>>(phi, out, nrows);
}

// round 14
// speedup vs baseline: 1.0471x; 1.0471x over previous
#include <cuda_runtime.h>
#include <cstdint>

// FWHT, 4096 rows x 16384 fp32. Persistent CTAs (grid=148, 1/SM), 1024 thr,
// register prefetch of next row (R6 structure, best measured) with butterfly
// stages packed into f32x2 (Blackwell packed-fp32): halves fma-pipe ops.
// Per-row dataflow:
//   P1: regs H16 over bits {13,12,1,0}  (float4 LDG; vector lanes = bits 1,0)
//   X1 -> P2: regs H16 over bits {11..8}  (same-address writeback)
//   X2 -> P3: regs H16 over bits {7..4}
//   shfl stages over bits {3,2}; scale 2^-7; coalesced STG.
// Swizzle phys(i) = i + 16*(i>>8): injective, 16B-aligned, conflict-free for
// all four smem patterns (verified R5-R13).

#define N_ELEM 16384
#define THREADS 1024
#define SMEM_FLOATS 17408  // max phys index 16383 + 16*63 = 17391
#define GRID 148

__device__ __forceinline__ int physz(int i) { return i + ((i >> 8) << 4); }

// H16 on 16 floats using packed f32x2 adds:
//   stage s=1: d = fma(p, (+1,-1), swap(p)) -> (v0+v1, v0-v1)
//   stages s'=1,2,4 on pairs: sum = add.f32x2, diff = fma(b, (-1,-1), a)
// 32 f32x2 fma-pipe ops replace 64 scalar FADD. Exact arithmetic (+-1 mults).
__device__ __forceinline__ void had16_fast(float* v) {
    const unsigned long long SGN  = 0xBF8000003F800000ULL;  // lo=+1.0, hi=-1.0
    const unsigned long long NEG1 = 0xBF800000BF800000ULL;  // (-1.0, -1.0)
    unsigned long long p[8];
#pragma unroll
    for (int k = 0; k < 8; k++) {
        unsigned long long pk, qk;
        asm("mov.b64 %0, {%1, %2};" : "=l"(pk) : "f"(v[2 * k]), "f"(v[2 * k + 1]));
        asm("mov.b64 %0, {%1, %2};" : "=l"(qk) : "f"(v[2 * k + 1]), "f"(v[2 * k]));
        asm("fma.rn.f32x2 %0, %1, %2, %3;"
            : "=l"(p[k]) : "l"(pk), "l"(SGN), "l"(qk));
    }
#pragma unroll
    for (int s = 1; s < 8; s <<= 1) {
#pragma unroll
        for (int k = 0; k < 8; k++) {
            if ((k & s) == 0) {
                unsigned long long a = p[k], b = p[k | s], su, di;
                asm("add.rn.f32x2 %0, %1, %2;" : "=l"(su) : "l"(a), "l"(b));
                asm("fma.rn.f32x2 %0, %1, %2, %3;"
                    : "=l"(di) : "l"(b), "l"(NEG1), "l"(a));
                p[k] = su; p[k | s] = di;
            }
        }
    }
#pragma unroll
    for (int k = 0; k < 8; k++)
        asm("mov.b64 {%0, %1}, %2;"
            : "=f"(v[2 * k]), "=f"(v[2 * k + 1]) : "l"(p[k]));
}

__global__ __launch_bounds__(THREADS, 1)
void fwht_kernel(const float* __restrict__ in, float* __restrict__ out,
                 int nrows) {
    extern __shared__ float sh[];
    const int t = threadIdx.x;
    const int l = t & 31;

    // Immediate-foldable bases:
    // P1: phys(j<<12 | t<<2)                = pa  + j*4352
    // P2: phys((t>>8)<<12 | r<<8 | (t&255)) = pb1 + r*272
    // P3: phys((t>>4)<<8  | r<<4 | (t&15))  = pb2 + r*16
    const int pa  = (t << 2) + ((t >> 6) << 4);
    const int pb1 = physz(((t >> 8) << 12) | (t & 255));
    const int b2  = ((t >> 4) << 8) | (t & 15);
    const int pb2 = physz(b2);

    const float s3 = (l & 8) ? -1.0f : 1.0f;
    const float s2 = (l & 4) ? -1.0f : 1.0f;

    float v[16];

    int row = blockIdx.x;
    {
        const float4* __restrict__ p4 =
            reinterpret_cast<const float4*>(in + (size_t)row * N_ELEM + (t << 2));
#pragma unroll
        for (int j = 0; j < 4; j++) {
            float4 f = p4[(size_t)j << 10];
            v[4 * j + 0] = f.x; v[4 * j + 1] = f.y;
            v[4 * j + 2] = f.z; v[4 * j + 3] = f.w;
        }
    }

    while (row < nrows) {
        const int nextrow = row + GRID;

        // ---- register prefetch: next row into vn (in flight during P1..P3)
        float vn[16];
        if (nextrow < nrows) {
            const float4* __restrict__ p4 =
                reinterpret_cast<const float4*>(in + (size_t)nextrow * N_ELEM + (t << 2));
#pragma unroll
            for (int j = 0; j < 4; j++) {
                float4 f = p4[(size_t)j << 10];
                vn[4 * j + 0] = f.x; vn[4 * j + 1] = f.y;
                vn[4 * j + 2] = f.z; vn[4 * j + 3] = f.w;
            }
        }

        // ---- P1: butterflies bits {13,12,1,0}; STS.128
        had16_fast(v);
#pragma unroll
        for (int j = 0; j < 4; j++) {
            *reinterpret_cast<float4*>(&sh[pa + j * 4352]) =
                make_float4(v[4 * j + 0], v[4 * j + 1], v[4 * j + 2], v[4 * j + 3]);
        }
        __syncthreads();  // B1

        // ---- P2: bits {11..8}; in-place (same-address) writeback
#pragma unroll
        for (int r = 0; r < 16; r++) v[r] = sh[pb1 + r * 272];
        had16_fast(v);
#pragma unroll
        for (int r = 0; r < 16; r++) sh[pb1 + r * 272] = v[r];
        __syncthreads();  // B2

        // ---- P3: bits {7..4}
#pragma unroll
        for (int r = 0; r < 16; r++) v[r] = sh[pb2 + r * 16];
        __syncthreads();  // B3: smem free for next iteration's P1 writes
        had16_fast(v);

        // ---- bits {3,2} on lane bits 3,2 via shfl-xor sign trick
#pragma unroll
        for (int r = 0; r < 16; r++) {
            float q = __shfl_xor_sync(0xffffffffu, v[r], 8);
            v[r] = fmaf(s3, v[r], q);
        }
#pragma unroll
        for (int r = 0; r < 16; r++) {
            float q = __shfl_xor_sync(0xffffffffu, v[r], 4);
            v[r] = fmaf(s2, v[r], q);
        }

        // ---- scale 2^-7, coalesced store (full 64B sectors)
        float* __restrict__ pout = out + (size_t)row * N_ELEM;
#pragma unroll
        for (int r = 0; r < 16; r++)
            pout[b2 + (r << 4)] = v[r] * 0.0078125f;

        // ---- rotate pipeline
        row = nextrow;
#pragma unroll
        for (int k = 0; k < 16; k++) v[k] = vn[k];
    }
}

extern "C" void kernel_launch(void* const* d_in, const int* in_sizes, int n_in,
                              void* d_out, int out_size) {
    const float* phi = (const float*)d_in[0];
    float* out = (float*)d_out;

    const size_t smem = SMEM_FLOATS * sizeof(float);  // 69632 B
    cudaFuncSetAttribute(fwht_kernel,
                         cudaFuncAttributeMaxDynamicSharedMemorySize,
                         (int)smem);

    const int nrows = in_sizes[0] / N_ELEM;  // 4096
    const int grid = nrows < GRID ? nrows : GRID;
    fwht_kernel<<<grid, THREADS, smem>>>(phi, out, nrows);
}

// round 15
// speedup vs baseline: 1.0628x; 1.0150x over previous
#include <cuda_runtime.h>

// FWHT, 4096 rows x 16384 fp32. Persistent CTAs (grid=148, 1/SM), 1024 thr,
// register prefetch of next row. R6 dataflow with RELAXED synchronization:
//   - double-buffered smem: removes the CTA-wide WAR barrier (B3)
//   - P2->P3 dependency is quarter-local (idx bits {13,12} = t>>8 for both
//     patterns), so B2 becomes a named barrier over 256 threads (bar.sync q+1)
// Per-row: 1 CTA barrier + 1 group-256 barrier (was 3 CTA-wide).
// Dataflow:
//   P1: regs H16 over bits {13,12,1,0}  (float4 LDG; vector lanes = bits 1,0)
//   X1 -> P2: regs H16 over bits {11..8}  (same-address writeback)
//   X2 -> P3: regs H16 over bits {7..4}
//   shfl stages over bits {3,2}; scale 2^-7; coalesced STG.
// Swizzle phys(i) = i + 16*(i>>8): injective, 16B-aligned, conflict-free for
// all four smem patterns (verified R5-R14).

#define N_ELEM 16384
#define THREADS 1024
#define BUF_FLOATS 17408   // max phys index 16383 + 16*63 = 17391
#define GRID 148

__device__ __forceinline__ int physz(int i) { return i + ((i >> 8) << 4); }

template <int N>
__device__ __forceinline__ void hadN(float* v) {
#pragma unroll
    for (int s = 1; s < N; s <<= 1) {
#pragma unroll
        for (int i = 0; i < N; i++) {
            if ((i & s) == 0) {
                float a = v[i];
                float b = v[i | s];
                v[i]     = a + b;
                v[i | s] = a - b;
            }
        }
    }
}

__global__ __launch_bounds__(THREADS, 1)
void fwht_kernel(const float* __restrict__ in, float* __restrict__ out,
                 int nrows) {
    extern __shared__ float sh[];
    const int t = threadIdx.x;
    const int l = t & 31;
    const int grp = t >> 8;  // quarter-group 0..3 (8 warps each)

    // Immediate-foldable bases:
    // P1: phys(j<<12 | t<<2)                = pa  + j*4352
    // P2: phys((t>>8)<<12 | r<<8 | (t&255)) = pb1 + r*272   (quarter t>>8)
    // P3: phys((t>>4)<<8  | r<<4 | (t&15))  = pb2 + r*16    (quarter t>>8)
    const int pa  = (t << 2) + ((t >> 6) << 4);
    const int pb1 = physz(((t >> 8) << 12) | (t & 255));
    const int b2  = ((t >> 4) << 8) | (t & 15);
    const int pb2 = physz(b2);

    const float s3 = (l & 8) ? -1.0f : 1.0f;
    const float s2 = (l & 4) ? -1.0f : 1.0f;

    float v[16];

    int row = blockIdx.x;
    {
        const float4* __restrict__ p4 =
            reinterpret_cast<const float4*>(in + (size_t)row * N_ELEM + (t << 2));
#pragma unroll
        for (int j = 0; j < 4; j++) {
            float4 f = p4[(size_t)j << 10];
            v[4 * j + 0] = f.x; v[4 * j + 1] = f.y;
            v[4 * j + 2] = f.z; v[4 * j + 3] = f.w;
        }
    }

    int p = 0;  // smem buffer parity
    while (row < nrows) {
        const int nextrow = row + GRID;
        float* __restrict__ buf = sh + p * BUF_FLOATS;

        // ---- register prefetch: next row into vn (in flight during P1..P3)
        float vn[16];
        if (nextrow < nrows) {
            const float4* __restrict__ p4 =
                reinterpret_cast<const float4*>(in + (size_t)nextrow * N_ELEM + (t << 2));
#pragma unroll
            for (int j = 0; j < 4; j++) {
                float4 f = p4[(size_t)j << 10];
                vn[4 * j + 0] = f.x; vn[4 * j + 1] = f.y;
                vn[4 * j + 2] = f.z; vn[4 * j + 3] = f.w;
            }
        }

        // ---- P1: butterflies bits {13,12,1,0}; STS.128 into buf[p]
        hadN<16>(v);
#pragma unroll
        for (int j = 0; j < 4; j++) {
            *reinterpret_cast<float4*>(&buf[pa + j * 4352]) =
                make_float4(v[4 * j + 0], v[4 * j + 1], v[4 * j + 2], v[4 * j + 3]);
        }
        __syncthreads();  // B1 (CTA): buf[p] fully written (writers scatter)

        // ---- P2: bits {11..8}; quarter-local; in-place writeback
#pragma unroll
        for (int r = 0; r < 16; r++) v[r] = buf[pb1 + r * 272];
        hadN<16>(v);
#pragma unroll
        for (int r = 0; r < 16; r++) buf[pb1 + r * 272] = v[r];

        // B2 (group-256): P2->P3 dependency confined to quarter t>>8
        asm volatile("bar.sync %0, %1;" :: "r"(grp + 1), "r"(256) : "memory");

        // ---- P3: bits {7..4}; quarter-local read; no WAR barrier needed
        //      (next row's P1 writes the OTHER buffer)
#pragma unroll
        for (int r = 0; r < 16; r++) v[r] = buf[pb2 + r * 16];
        hadN<16>(v);

        // ---- bits {3,2} on lane bits 3,2 via shfl-xor sign trick
#pragma unroll
        for (int r = 0; r < 16; r++) {
            float q = __shfl_xor_sync(0xffffffffu, v[r], 8);
            v[r] = fmaf(s3, v[r], q);
        }
#pragma unroll
        for (int r = 0; r < 16; r++) {
            float q = __shfl_xor_sync(0xffffffffu, v[r], 4);
            v[r] = fmaf(s2, v[r], q);
        }

        // ---- scale 2^-7, coalesced store (full 64B sectors)
        float* __restrict__ pout = out + (size_t)row * N_ELEM;
#pragma unroll
        for (int r = 0; r < 16; r++)
            pout[b2 + (r << 4)] = v[r] * 0.0078125f;

        // ---- rotate pipeline
        row = nextrow;
        p ^= 1;
#pragma unroll
        for (int k = 0; k < 16; k++) v[k] = vn[k];
    }
}

extern "C" void kernel_launch(void* const* d_in, const int* in_sizes, int n_in,
                              void* d_out, int out_size) {
    const float* phi = (const float*)d_in[0];
    float* out = (float*)d_out;

    const size_t smem = 2 * BUF_FLOATS * sizeof(float);  // 139264 B
    cudaFuncSetAttribute(fwht_kernel,
                         cudaFuncAttributeMaxDynamicSharedMemorySize,
                         (int)smem);

    const int nrows = in_sizes[0] / N_ELEM;  // 4096
    const int grid = nrows < GRID ? nrows : GRID;
    fwht_kernel<<<grid, THREADS, smem>>>(phi, out, nrows);
}

// round 16
// speedup vs baseline: 1.1162x; 1.0502x over previous
#include <cuda_runtime.h>

// FWHT, 4096 rows x 16384 fp32. Persistent CTAs (grid=148, 1/SM), 1024 thr,
// register prefetch of next row; relaxed sync (R15) + streaming cache hints:
//   - input loads via __ldcs (read-once, evict-first)
//   - output stores via __stcs (write-once streaming; don't thrash L2)
// Per-row: 1 CTA barrier + 1 group-256 barrier; double-buffered smem.
// Dataflow:
//   P1: regs H16 over bits {13,12,1,0}  (float4 LDG; vector lanes = bits 1,0)
//   X1 -> P2: regs H16 over bits {11..8}  (same-address writeback)
//   X2 -> P3: regs H16 over bits {7..4}
//   shfl stages over bits {3,2}; scale 2^-7; coalesced STG.
// Swizzle phys(i) = i + 16*(i>>8): injective, 16B-aligned, conflict-free for
// all four smem patterns (verified R5-R15).

#define N_ELEM 16384
#define THREADS 1024
#define BUF_FLOATS 17408   // max phys index 16383 + 16*63 = 17391
#define GRID 148

__device__ __forceinline__ int physz(int i) { return i + ((i >> 8) << 4); }

template <int N>
__device__ __forceinline__ void hadN(float* v) {
#pragma unroll
    for (int s = 1; s < N; s <<= 1) {
#pragma unroll
        for (int i = 0; i < N; i++) {
            if ((i & s) == 0) {
                float a = v[i];
                float b = v[i | s];
                v[i]     = a + b;
                v[i | s] = a - b;
            }
        }
    }
}

__global__ __launch_bounds__(THREADS, 1)
void fwht_kernel(const float* __restrict__ in, float* __restrict__ out,
                 int nrows) {
    extern __shared__ float sh[];
    const int t = threadIdx.x;
    const int l = t & 31;
    const int grp = t >> 8;  // quarter-group 0..3 (8 warps each)

    // Immediate-foldable bases:
    // P1: phys(j<<12 | t<<2)                = pa  + j*4352
    // P2: phys((t>>8)<<12 | r<<8 | (t&255)) = pb1 + r*272   (quarter-local)
    // P3: phys((t>>4)<<8  | r<<4 | (t&15))  = pb2 + r*16    (quarter-local)
    const int pa  = (t << 2) + ((t >> 6) << 4);
    const int pb1 = physz(((t >> 8) << 12) | (t & 255));
    const int b2  = ((t >> 4) << 8) | (t & 15);
    const int pb2 = physz(b2);

    const float s3 = (l & 8) ? -1.0f : 1.0f;
    const float s2 = (l & 4) ? -1.0f : 1.0f;

    float v[16];

    int row = blockIdx.x;
    {
        const float4* __restrict__ p4 =
            reinterpret_cast<const float4*>(in + (size_t)row * N_ELEM + (t << 2));
#pragma unroll
        for (int j = 0; j < 4; j++) {
            float4 f = __ldcs(&p4[(size_t)j << 10]);
            v[4 * j + 0] = f.x; v[4 * j + 1] = f.y;
            v[4 * j + 2] = f.z; v[4 * j + 3] = f.w;
        }
    }

    int p = 0;  // smem buffer parity
    while (row < nrows) {
        const int nextrow = row + GRID;
        float* __restrict__ buf = sh + p * BUF_FLOATS;

        // ---- register prefetch: next row into vn (in flight during P1..P3)
        float vn[16];
        if (nextrow < nrows) {
            const float4* __restrict__ p4 =
                reinterpret_cast<const float4*>(in + (size_t)nextrow * N_ELEM + (t << 2));
#pragma unroll
            for (int j = 0; j < 4; j++) {
                float4 f = __ldcs(&p4[(size_t)j << 10]);
                vn[4 * j + 0] = f.x; vn[4 * j + 1] = f.y;
                vn[4 * j + 2] = f.z; vn[4 * j + 3] = f.w;
            }
        }

        // ---- P1: butterflies bits {13,12,1,0}; STS.128 into buf[p]
        hadN<16>(v);
#pragma unroll
        for (int j = 0; j < 4; j++) {
            *reinterpret_cast<float4*>(&buf[pa + j * 4352]) =
                make_float4(v[4 * j + 0], v[4 * j + 1], v[4 * j + 2], v[4 * j + 3]);
        }
        __syncthreads();  // B1 (CTA): buf[p] fully written (writers scatter)

        // ---- P2: bits {11..8}; quarter-local; in-place writeback
#pragma unroll
        for (int r = 0; r < 16; r++) v[r] = buf[pb1 + r * 272];
        hadN<16>(v);
#pragma unroll
        for (int r = 0; r < 16; r++) buf[pb1 + r * 272] = v[r];

        // B2 (group-256): P2->P3 dependency confined to quarter t>>8
        asm volatile("bar.sync %0, %1;" :: "r"(grp + 1), "r"(256) : "memory");

        // ---- P3: bits {7..4}; quarter-local read; no WAR barrier needed
        //      (next row's P1 writes the OTHER buffer)
#pragma unroll
        for (int r = 0; r < 16; r++) v[r] = buf[pb2 + r * 16];
        hadN<16>(v);

        // ---- bits {3,2} on lane bits 3,2 via shfl-xor sign trick
#pragma unroll
        for (int r = 0; r < 16; r++) {
            float q = __shfl_xor_sync(0xffffffffu, v[r], 8);
            v[r] = fmaf(s3, v[r], q);
        }
#pragma unroll
        for (int r = 0; r < 16; r++) {
            float q = __shfl_xor_sync(0xffffffffu, v[r], 4);
            v[r] = fmaf(s2, v[r], q);
        }

        // ---- scale 2^-7, streaming store (full 64B sectors, evict-first)
        float* __restrict__ pout = out + (size_t)row * N_ELEM;
#pragma unroll
        for (int r = 0; r < 16; r++)
            __stcs(&pout[b2 + (r << 4)], v[r] * 0.0078125f);

        // ---- rotate pipeline
        row = nextrow;
        p ^= 1;
#pragma unroll
        for (int k = 0; k < 16; k++) v[k] = vn[k];
    }
}

extern "C" void kernel_launch(void* const* d_in, const int* in_sizes, int n_in,
                              void* d_out, int out_size) {
    const float* phi = (const float*)d_in[0];
    float* out = (float*)d_out;

    const size_t smem = 2 * BUF_FLOATS * sizeof(float);  // 139264 B
    cudaFuncSetAttribute(fwht_kernel,
                         cudaFuncAttributeMaxDynamicSharedMemorySize,
                         (int)smem);

    const int nrows = in_sizes[0] / N_ELEM;  // 4096
    const int grid = nrows < GRID ? nrows : GRID;
    fwht_kernel<<<grid, THREADS, smem>>>(phi, out, nrows);
}

// round 17
// speedup vs baseline: 1.1278x; 1.0104x over previous
#include <cuda_runtime.h>

// FWHT, 4096 rows x 16384 fp32. Persistent CTAs (grid=148, 1/SM), 1024 thr,
// register prefetch, streaming cache hints (__ldcs/__stcs), double-buffered
// smem, and STAGGERED piece barriers: P1 writes piece j (idx bits{13,12}=j),
// then bar.arrive(1+j) -- except a thread's own group piece where it
// bar.sync(1+j). Group g's P2/P3 touch ONLY piece g, so group 0 starts its
// back-half while groups 1-3 still write -> quarter-groups pipeline through
// the row in a wavefront instead of lockstep.
// Dataflow:
//   P1: regs H16 over bits {13,12,1,0}  (float4 LDG; vector lanes = bits 1,0)
//   X1 -> P2: regs H16 over bits {11..8}  (same-address writeback, piece grp)
//   X2 -> P3: regs H16 over bits {7..4}   (piece grp)
//   shfl stages over bits {3,2}; scale 2^-7; streaming STG.
// Swizzle phys(i) = i + 16*(i>>8): injective, 16B-aligned, conflict-free for
// all four smem patterns (verified R5-R16).
// Named barriers: 1..4 = piece barriers (count 1024), 5..8 = group B2 (256).

#define N_ELEM 16384
#define THREADS 1024
#define BUF_FLOATS 17408   // max phys index 16383 + 16*63 = 17391
#define GRID 148

__device__ __forceinline__ int physz(int i) { return i + ((i >> 8) << 4); }

template <int N>
__device__ __forceinline__ void hadN(float* v) {
#pragma unroll
    for (int s = 1; s < N; s <<= 1) {
#pragma unroll
        for (int i = 0; i < N; i++) {
            if ((i & s) == 0) {
                float a = v[i];
                float b = v[i | s];
                v[i]     = a + b;
                v[i | s] = a - b;
            }
        }
    }
}

__device__ __forceinline__ void bar_sync_n(int id, int cnt) {
    asm volatile("bar.sync %0, %1;" :: "r"(id), "r"(cnt) : "memory");
}
__device__ __forceinline__ void bar_arrive_n(int id, int cnt) {
    asm volatile("bar.arrive %0, %1;" :: "r"(id), "r"(cnt) : "memory");
}

__global__ __launch_bounds__(THREADS, 1)
void fwht_kernel(const float* __restrict__ in, float* __restrict__ out,
                 int nrows) {
    extern __shared__ float sh[];
    const int t = threadIdx.x;
    const int l = t & 31;
    const int grp = t >> 8;  // quarter-group 0..3 (8 warps each)

    // Immediate-foldable bases:
    // P1: phys(j<<12 | t<<2)                = pa  + j*4352  (piece j)
    // P2: phys(grp<<12 | r<<8 | (t&255))    = pb1 + r*272   (piece grp)
    // P3: phys(grp<<12 | ... | r<<4 | t&15) = pb2 + r*16    (piece grp)
    const int pa  = (t << 2) + ((t >> 6) << 4);
    const int pb1 = physz((grp << 12) | (t & 255));
    const int b2  = ((t >> 4) << 8) | (t & 15);
    const int pb2 = physz(b2);

    const float s3 = (l & 8) ? -1.0f : 1.0f;
    const float s2 = (l & 4) ? -1.0f : 1.0f;

    float v[16];

    int row = blockIdx.x;
    {
        const float4* __restrict__ p4 =
            reinterpret_cast<const float4*>(in + (size_t)row * N_ELEM + (t << 2));
#pragma unroll
        for (int j = 0; j < 4; j++) {
            float4 f = __ldcs(&p4[(size_t)j << 10]);
            v[4 * j + 0] = f.x; v[4 * j + 1] = f.y;
            v[4 * j + 2] = f.z; v[4 * j + 3] = f.w;
        }
    }

    int p = 0;  // smem buffer parity
    while (row < nrows) {
        const int nextrow = row + GRID;
        float* __restrict__ buf = sh + p * BUF_FLOATS;

        // ---- register prefetch: next row into vn (in flight during P1..P3)
        float vn[16];
        if (nextrow < nrows) {
            const float4* __restrict__ p4 =
                reinterpret_cast<const float4*>(in + (size_t)nextrow * N_ELEM + (t << 2));
#pragma unroll
            for (int j = 0; j < 4; j++) {
                float4 f = __ldcs(&p4[(size_t)j << 10]);
                vn[4 * j + 0] = f.x; vn[4 * j + 1] = f.y;
                vn[4 * j + 2] = f.z; vn[4 * j + 3] = f.w;
            }
        }

        // ---- P1: butterflies bits {13,12,1,0}; staggered piece writes.
        // After writing piece j every thread arrives at barrier 1+j; the
        // group that consumes piece j (grp==j) syncs instead. 768 arrivals +
        // 256 syncs = 1024. bar.arrive releases this thread's STS to the
        // synced consumers (producer/consumer named-barrier pattern).
        hadN<16>(v);
#pragma unroll
        for (int j = 0; j < 4; j++) {
            *reinterpret_cast<float4*>(&buf[pa + j * 4352]) =
                make_float4(v[4 * j + 0], v[4 * j + 1], v[4 * j + 2], v[4 * j + 3]);
            if (j == grp) bar_sync_n(1 + j, THREADS);
            else          bar_arrive_n(1 + j, THREADS);
        }

        // ---- P2: bits {11..8}; piece grp only; in-place writeback
#pragma unroll
        for (int r = 0; r < 16; r++) v[r] = buf[pb1 + r * 272];
        hadN<16>(v);
#pragma unroll
        for (int r = 0; r < 16; r++) buf[pb1 + r * 272] = v[r];

        // B2 (group-256): P2->P3 dependency confined to piece grp
        bar_sync_n(5 + grp, 256);

        // ---- P3: bits {7..4}; piece grp only; no WAR barrier needed
        //      (next row's P1 writes the OTHER buffer; drift bounded <=1 row)
#pragma unroll
        for (int r = 0; r < 16; r++) v[r] = buf[pb2 + r * 16];
        hadN<16>(v);

        // ---- bits {3,2} on lane bits 3,2 via shfl-xor sign trick
#pragma unroll
        for (int r = 0; r < 16; r++) {
            float q = __shfl_xor_sync(0xffffffffu, v[r], 8);
            v[r] = fmaf(s3, v[r], q);
        }
#pragma unroll
        for (int r = 0; r < 16; r++) {
            float q = __shfl_xor_sync(0xffffffffu, v[r], 4);
            v[r] = fmaf(s2, v[r], q);
        }

        // ---- scale 2^-7, streaming store (full 64B sectors, evict-first)
        float* __restrict__ pout = out + (size_t)row * N_ELEM;
#pragma unroll
        for (int r = 0; r < 16; r++)
            __stcs(&pout[b2 + (r << 4)], v[r] * 0.0078125f);

        // ---- rotate pipeline
        row = nextrow;
        p ^= 1;
#pragma unroll
        for (int k = 0; k < 16; k++) v[k] = vn[k];
    }
}

extern "C" void kernel_launch(void* const* d_in, const int* in_sizes, int n_in,
                              void* d_out, int out_size) {
    const float* phi = (const float*)d_in[0];
    float* out = (float*)d_out;

    const size_t smem = 2 * BUF_FLOATS * sizeof(float);  // 139264 B
    cudaFuncSetAttribute(fwht_kernel,
                         cudaFuncAttributeMaxDynamicSharedMemorySize,
                         (int)smem);

    const int nrows = in_sizes[0] / N_ELEM;  // 4096
    const int grid = nrows < GRID ? nrows : GRID;
    fwht_kernel<<<grid, THREADS, smem>>>(phi, out, nrows);
}